// round 1
// baseline (speedup 1.0000x reference)
#include <cuda_runtime.h>
#include <cuda_bf16.h>

// Semi-CRF forward DP (HSCRF). B=16, L=128, T=11, K=7.
// start_id = T-1 = 10, stop_id = T-2 = 9.
//
// Three launches:
//  1. prepass: P[b][e][k][yp][y] = exp(scores[b, e-6+k, e, yp, y]) (0 if j<0)
//  2. dp: per-batch sequential recurrence in exp domain with running log-scale
//  3. reduce: sum 16 per-batch results into d_out[0]

#define B_ 16
#define L_ 128
#define T_ 11
#define K_ 7
#define TT_ 121
#define NTOT (B_ * L_ * K_ * TT_)

__device__ float g_P[NTOT];       // 6.94 MB scratch (static, allocation-free)
__device__ float g_partial[B_];

__global__ void __launch_bounds__(256) prepass_kernel(const float* __restrict__ scores) {
    int idx = blockIdx.x * blockDim.x + threadIdx.x;
    if (idx >= NTOT) return;
    int q  = idx % TT_;        // yp*T + y
    int r  = idx / TT_;
    int k  = r % K_;
    int r2 = r / K_;
    int e  = r2 % L_;          // end position (0..L-1), alpha step i = e+1
    int b  = r2 / L_;
    int j  = e - (K_ - 1) + k; // span start / alpha index used
    float v = 0.f;
    if (j >= 0) {
        // scores[b][j][e][yp][y], contiguous over q -> coalesced 484B runs
        v = __expf(scores[((b * L_ + j) * L_ + e) * TT_ + q]);
    }
    g_P[idx] = v;              // fully coalesced write
}

__global__ void __launch_bounds__(128) dp_kernel(const int* __restrict__ mask) {
    const int b   = blockIdx.x;
    const int tid = threadIdx.x;

    __shared__ float u_ring[K_][16];  // exp-domain alpha, normalized; padded row
    __shared__ float m_ring[K_];      // log-scale per ring slot
    __shared__ float e_s[K_];         // exp(m[slot] - M) per step
    __shared__ float part_s[TT_];     // per-(yp,y) partial sums

    // init: alpha_0[start_id=10] = 0 -> u=1, m=0; sentinel slots m=-1e30, u=0
    if (tid < K_) m_ring[tid] = (tid == 0) ? 0.f : -1e30f;
    if (tid < K_ * 16) {
        int s = tid >> 4, c = tid & 15;
        u_ring[s][c] = (s == 0 && c == (T_ - 1)) ? 1.f : 0.f;
    }

    const int len = mask[b];                  // in [64, 128]
    const float* Pb = g_P + b * (L_ * K_ * TT_);
    const int yp = tid / T_;                  // valid for tid < 121
    float res = 0.f;

    // preload P for e=0 (double buffer)
    float Pc[K_];
#pragma unroll
    for (int k = 0; k < K_; k++) Pc[k] = (tid < TT_) ? __ldg(&Pb[k * TT_ + tid]) : 0.f;
    __syncthreads();

    for (int e = 0; e < L_; e++) {
        const int i  = e + 1;
        const int sn = i % K_;  // ring slot to write; also slot of k=0 (js = e-6)

        // prefetch next step's P (L2-resident; hidden behind this step's body)
        float Pn[K_];
        const int en = (e < L_ - 1) ? e + 1 : e;
#pragma unroll
        for (int k = 0; k < K_; k++)
            Pn[k] = (tid < TT_) ? __ldg(&Pb[(en * K_ + k) * TT_ + tid]) : 0.f;

        // window max of log-scales + per-slot scale factors (warp 0)
        float M = 0.f;
        if (tid < 32) {
            M = m_ring[0];
#pragma unroll
            for (int s = 1; s < K_; s++) M = fmaxf(M, m_ring[s]);
            if (tid < K_) e_s[tid] = __expf(m_ring[tid] - M);  // sentinel -> 0
        }
        __syncthreads();

        // GEMV: partial[yp][y] = sum_k P[k][yp][y] * e_s[slot(k)] * u[slot(k)][yp]
        if (tid < TT_) {
            float acc = 0.f;
#pragma unroll
            for (int k = 0; k < K_; k++) {
                int s = sn + k; if (s >= K_) s -= K_;   // slot of js = e-6+k
                acc = fmaf(Pc[k], e_s[s] * u_ring[s][yp], acc);
            }
            part_s[tid] = acc;
        }
        __syncthreads();

        // reduce over yp, renormalize, update ring (warp 0 only)
        if (tid < 32) {
            float S = 0.f;
            if (tid < T_) {
                float v0 = part_s[0*T_+tid], v1 = part_s[1*T_+tid], v2 = part_s[2*T_+tid],
                      v3 = part_s[3*T_+tid], v4 = part_s[4*T_+tid], v5 = part_s[5*T_+tid],
                      v6 = part_s[6*T_+tid], v7 = part_s[7*T_+tid], v8 = part_s[8*T_+tid],
                      v9 = part_s[9*T_+tid], v10 = part_s[10*T_+tid];
                S = ((v0 + v1) + (v2 + v3)) + ((v4 + v5) + (v6 + v7)) + ((v8 + v9) + v10);
            }
            // alpha_i[stop] = M + ln(S[stop]); capture at i == len
            if (tid == (T_ - 2) && i == len) res = M + __logf(S);
            // normalizer: S[y=0] (always > 0, within e^~15 of max -> safe scale)
            float c = __shfl_sync(0xffffffffu, S, 0);
            if (tid < T_) u_ring[sn][tid] = __fdividef(S, c);
            if (tid == 0) m_ring[sn] = M + __logf(c);
        }
        __syncthreads();

#pragma unroll
        for (int k = 0; k < K_; k++) Pc[k] = Pn[k];
    }

    if (tid == (T_ - 2)) g_partial[b] = res;
}

__global__ void reduce_kernel(float* __restrict__ out) {
    if (threadIdx.x == 0) {
        float s = 0.f;
#pragma unroll
        for (int b = 0; b < B_; b++) s += g_partial[b];
        out[0] = s;
    }
}

extern "C" void kernel_launch(void* const* d_in, const int* in_sizes, int n_in,
                              void* d_out, int out_size) {
    const float* scores = (const float*)d_in[0];
    const int*   mask   = (const int*)d_in[1];

    prepass_kernel<<<(NTOT + 255) / 256, 256>>>(scores);
    dp_kernel<<<B_, 128>>>(mask);
    reduce_kernel<<<1, 32>>>((float*)d_out);
}

// round 2
// speedup vs baseline: 1.3905x; 1.3905x over previous
#include <cuda_runtime.h>
#include <cuda_bf16.h>

// Semi-CRF forward DP (HSCRF). B=16, L=128, T=11, K=7.
// Single fused kernel: log2-domain recurrence, exp folded inline (no prepass,
// no scratch), 192 threads/block mapped (y, yp) in 16-wide segments,
// ONE __syncthreads per step (ring-of-8 makes write slot disjoint from reads).

#define B_ 16
#define L_ 128
#define T_ 11
#define K_ 7
#define TT_ 121
#define NEGBIG  (-1e30f)
#define LOG2E_F 1.4426950408889634f
#define LN2_F   0.6931471805599453f

__device__ float g_partial[B_];

__device__ __forceinline__ float ex2f(float x) {
    float r; asm("ex2.approx.ftz.f32 %0, %1;" : "=f"(r) : "f"(x)); return r;
}
__device__ __forceinline__ float lg2f(float x) {
    float r; asm("lg2.approx.f32 %0, %1;" : "=f"(r) : "f"(x)); return r;
}

__global__ void __launch_bounds__(192) dp_kernel(const float* __restrict__ scores,
                                                 const int* __restrict__ mask) {
    const int b   = blockIdx.x;
    const int tid = threadIdx.x;
    const int y   = tid >> 4;      // 0..11 (y==11 -> idle segment)
    const int yp  = tid & 15;      // 0..15 (yp>=11 -> padding lanes)
    const bool act = (y < T_) && (yp < T_);
    const int q   = yp * T_ + y;   // flat (yp, y) index into last two dims

    __shared__ float a_ring[8][16];  // alpha (log2 domain), [slot][label]
    __shared__ float r_ring[8];      // per-slot row-max proxy (log2 domain)

    // init: alpha_0[start=T-1] = 0, other labels = -10000 (natural) -> *log2e
    if (tid < 8) r_ring[tid] = (tid == 0) ? 0.f : NEGBIG;
    if (tid < 128) {
        int s = tid >> 4, c = tid & 15;
        a_ring[s][c] = (s == 0) ? ((c == T_ - 1) ? 0.f : -10000.f * LOG2E_F)
                                : NEGBIG;
    }

    const int len = mask[b];  // in [64, 128]
    const float* base = scores + (size_t)b * (L_ * L_ * TT_) + q;

    // distance-2 register prefetch of scores: sA = step e, sB = e+1, sC = e+2
    float sA[K_], sB[K_], sC[K_];
#pragma unroll
    for (int k = 0; k < K_; k++) {
        int j0 = k - (K_ - 1);                 // e = 0
        sA[k] = (act && j0 >= 0) ? __ldg(base + (j0 * L_ + 0) * TT_) : NEGBIG;
        int j1 = k - (K_ - 2);                 // e = 1
        sB[k] = (act && j1 >= 0) ? __ldg(base + (j1 * L_ + 1) * TT_) : NEGBIG;
    }
    __syncthreads();

    float res = 0.f;

    for (int e = 0; e < L_; e++) {
        const int i  = e + 1;
        const int sn = i & 7;

        // prefetch scores for step e+2 (DRAM latency hidden across 2 steps)
        const int en = e + 2;
#pragma unroll
        for (int k = 0; k < K_; k++) {
            int j = en - (K_ - 1) + k;
            sC[k] = NEGBIG;
            if (act && en < L_ && j >= 0)
                sC[k] = __ldg(base + (j * L_ + en) * TT_);
        }

        // window max over all 8 slots (superset of the 7 valid; stale slot is
        // always <= window max for growing alphas -> safe upper bound for M)
        float M = r_ring[0];
#pragma unroll
        for (int s = 1; s < 8; s++) M = fmaxf(M, r_ring[s]);

        // acc = sum_k exp2(s_k*log2e + a[j_k][yp] - M); masked terms -> 0
        float acc0 = 0.f, acc1 = 0.f;
        if (act) {
#pragma unroll
            for (int k = 0; k < K_; k++) {
                int s = (i - K_ + k) & 7;       // ring slot of j = i-7+k
                float t = ex2f(fmaf(sA[k], LOG2E_F, a_ring[s][yp] - M));
                if (k & 1) acc1 += t; else acc0 += t;
            }
        }
        float acc = acc0 + acc1;

        // reduce over yp within the 16-wide segment (half-warp shuffles)
        acc += __shfl_xor_sync(0xffffffffu, acc, 8, 16);
        acc += __shfl_xor_sync(0xffffffffu, acc, 4, 16);
        acc += __shfl_xor_sync(0xffffffffu, acc, 2, 16);
        acc += __shfl_xor_sync(0xffffffffu, acc, 1, 16);

        // segment leaders write the new alpha row (slot sn is disjoint from
        // all slots read this step -> no extra barrier needed before writing)
        if (yp == 0 && y < T_) {
            float an = M + lg2f(acc);
            a_ring[sn][y] = an;
            if (y == 0) r_ring[sn] = an;              // row-max proxy
            if (y == T_ - 2 && i == len) res = an;    // stop label at i = len
        }

        // rotate prefetch buffers
#pragma unroll
        for (int k = 0; k < K_; k++) { sA[k] = sB[k]; sB[k] = sC[k]; }

        __syncthreads();
    }

    if (y == T_ - 2 && yp == 0) g_partial[b] = res * LN2_F;  // back to natural log
}

__global__ void reduce_kernel(float* __restrict__ out) {
    if (threadIdx.x == 0) {
        float s = 0.f;
#pragma unroll
        for (int b = 0; b < B_; b++) s += g_partial[b];
        out[0] = s;
    }
}

extern "C" void kernel_launch(void* const* d_in, const int* in_sizes, int n_in,
                              void* d_out, int out_size) {
    const float* scores = (const float*)d_in[0];
    const int*   mask   = (const int*)d_in[1];

    dp_kernel<<<B_, 192>>>(scores, mask);
    reduce_kernel<<<1, 32>>>((float*)d_out);
}

// round 3
// speedup vs baseline: 1.5061x; 1.0832x over previous
#include <cuda_runtime.h>
#include <cuda_bf16.h>

// Semi-CRF forward DP (HSCRF). B=16, L=128, T=11, K=7.
// Single fused kernel: log2-domain recurrence, exp folded inline, 192 threads
// mapped (y, yp) in 16-wide segments, ONE __syncthreads per step.
// R3: register-carried alpha window (1 LDS/step), single-LDS scale proxy M,
// distance-3 score prefetch, in-kernel last-block reduction (no 2nd kernel).

#define B_ 16
#define L_ 128
#define T_ 11
#define K_ 7
#define TT_ 121
#define NEGBIG  (-1e30f)
#define LOG2E_F 1.4426950408889634f
#define LN2_F   0.6931471805599453f

__device__ float g_partial[B_];
__device__ unsigned int g_tickets;   // module-lifetime; one winner per launch

__device__ __forceinline__ float ex2f(float x) {
    float r; asm("ex2.approx.ftz.f32 %0, %1;" : "=f"(r) : "f"(x)); return r;
}
__device__ __forceinline__ float lg2f(float x) {
    float r; asm("lg2.approx.f32 %0, %1;" : "=f"(r) : "f"(x)); return r;
}

__global__ void __launch_bounds__(192) dp_kernel(const float* __restrict__ scores,
                                                 const int* __restrict__ mask,
                                                 float* __restrict__ out) {
    const int b   = blockIdx.x;
    const int tid = threadIdx.x;
    const int y   = tid >> 4;      // 0..11 (y==11 -> idle segment)
    const int yp  = tid & 15;      // 0..15 (yp>=11 -> padding lanes)
    const bool act = (y < T_) && (yp < T_);
    const int q   = yp * T_ + y;   // flat (yp, y) index into last two dims

    __shared__ float a_ring[8][16];  // alpha (log2 domain), [slot][label]
    __shared__ float r_ring[8];      // per-slot scale proxy (a[s][0], log2)

    // init: alpha_0[start=T-1] = 0, other labels -10000 nats; slots 1..7 sentinel
    if (tid < 8) r_ring[tid] = (tid == 0) ? 0.f : NEGBIG;
    if (tid < 128) {
        int s = tid >> 4, c = tid & 15;
        a_ring[s][c] = (s == 0) ? ((c == T_ - 1) ? 0.f : -10000.f * LOG2E_F)
                                : NEGBIG;
    }

    const int len = mask[b];  // in [64, 128]
    const float* base = scores + (size_t)b * (L_ * L_ * TT_) + q;

    // distance-3 register prefetch: s0 = step e, s1 = e+1, s2 = e+2
    float s0[K_], s1[K_], s2[K_], s3[K_];
#pragma unroll
    for (int k = 0; k < K_; k++) {
        int j0 = k - (K_ - 1);
        s0[k] = (act && j0 >= 0) ? __ldg(base + (j0 * L_ + 0) * TT_) : NEGBIG;
        int j1 = k - (K_ - 2);
        s1[k] = (act && j1 >= 0) ? __ldg(base + (j1 * L_ + 1) * TT_) : NEGBIG;
        int j2 = k - (K_ - 3);
        s2[k] = (act && j2 >= 0) ? __ldg(base + (j2 * L_ + 2) * TT_) : NEGBIG;
    }

    // register-carried alpha window: av[k] <-> alpha[i-7+k][yp]
    float av[K_];
#pragma unroll
    for (int k = 0; k < K_; k++) av[k] = NEGBIG;

    float res = 0.f;
    __syncthreads();

    for (int e = 0; e < len; e++) {
        const int i  = e + 1;
        const int sn = i & 7;

        // slide window: one new alpha row (written last step), one scale proxy.
        // slot e&7 is disjoint from this step's write slot sn -> no race.
#pragma unroll
        for (int k = 0; k < K_ - 1; k++) av[k] = av[k + 1];
        av[K_ - 1] = a_ring[e & 7][yp];
        const float M = r_ring[e & 7];   // warp-uniform broadcast LDS

        // prefetch scores for step e+3
        const int en = e + 3;
#pragma unroll
        for (int k = 0; k < K_; k++) {
            int j = en - (K_ - 1) + k;
            s3[k] = NEGBIG;
            if (act && en < len && j >= 0)
                s3[k] = __ldg(base + (j * L_ + en) * TT_);
        }

        // acc = sum_k exp2(s_k*log2e + a_k - M); masked terms underflow to 0
        float acc0 = 0.f, acc1 = 0.f;
        if (act) {
#pragma unroll
            for (int k = 0; k < K_; k++) {
                float t = ex2f(fmaf(s0[k], LOG2E_F, av[k] - M));
                if (k & 1) acc1 += t; else acc0 += t;
            }
        }
        float acc = acc0 + acc1;

        // reduce over yp within the 16-wide segment
        acc += __shfl_xor_sync(0xffffffffu, acc, 8, 16);
        acc += __shfl_xor_sync(0xffffffffu, acc, 4, 16);
        acc += __shfl_xor_sync(0xffffffffu, acc, 2, 16);
        acc += __shfl_xor_sync(0xffffffffu, acc, 1, 16);

        // segment leaders write the new alpha row (slot sn disjoint from reads)
        if (yp == 0 && y < T_) {
            float an = M + lg2f(acc);
            a_ring[sn][y] = an;
            if (y == 0) r_ring[sn] = an;              // scale proxy
            if (y == T_ - 2 && i == len) res = an;    // stop label at i = len
        }

        // rotate prefetch buffers
#pragma unroll
        for (int k = 0; k < K_; k++) { s0[k] = s1[k]; s1[k] = s2[k]; s2[k] = s3[k]; }

        __syncthreads();
    }

    if (y == T_ - 2 && yp == 0) g_partial[b] = res * LN2_F;  // back to natural log
    __syncthreads();

    // last-finishing block sums the 16 partials (no separate reduce launch)
    if (tid == 0) {
        __threadfence();
        unsigned old = atomicAdd(&g_tickets, 1u);
        if ((old & (B_ - 1)) == (B_ - 1)) {
            __threadfence();
            float s = 0.f;
#pragma unroll
            for (int bb = 0; bb < B_; bb++)
                s += *((volatile float*)&g_partial[bb]);
            out[0] = s;
        }
    }
}

extern "C" void kernel_launch(void* const* d_in, const int* in_sizes, int n_in,
                              void* d_out, int out_size) {
    const float* scores = (const float*)d_in[0];
    const int*   mask   = (const int*)d_in[1];

    dp_kernel<<<B_, 192>>>(scores, mask, (float*)d_out);
}